// round 12
// baseline (speedup 1.0000x reference)
#include <cuda_runtime.h>
#include <math.h>

#define NPTS 4096
#define KN   30
#define HID  32
#define GD   16
#define NCELL 256
#define CAP  64
#define TPB  512
#define WARPS 16
#define QPW  4
#define MAXNU 8
#define FULL 0xffffffffu
#define MAXK 0xffffffffffffffffULL
#define PI_F 3.14159265358979f
#define TWO_LOG2E 2.885390081777927f   // 2*log2(e)

__device__ float2         g_xy[MAXNU][NPTS];
__device__ unsigned short g_id[MAXNU][NPTS];
__device__ int            g_cs[MAXNU][NCELL + 1];

// FROZEN reference rounding chain (validated bit-exact R7-R11):
//   pn = rn( rn(px*px) + rn(py*py) )
//   t  = fma(qy,py, rn(qx*px))
//   d2 = rn( rn(qn - 2t) + pn )
__device__ __forceinline__ float d2_ref(float qxx, float qyy, float qn,
                                        float px, float py) {
    float pn = __fadd_rn(__fmul_rn(px, px), __fmul_rn(py, py));
    float t  = __fmaf_rn(qyy, py, __fmul_rn(qxx, px));
    return __fadd_rn(__fsub_rn(qn, __fmul_rn(2.0f, t)), pn);
}

__device__ __forceinline__ unsigned fkey(float f) {
    unsigned u = __float_as_uint(f);
    return u ^ (unsigned)(((int)u >> 31) | 0x80000000);
}

__device__ __forceinline__ float ex2(float x) {
    float r; asm("ex2.approx.f32 %0, %1;" : "=f"(r) : "f"(x)); return r;
}
__device__ __forceinline__ float rcp(float x) {
    float r; asm("rcp.approx.f32 %0, %1;" : "=f"(r) : "f"(x)); return r;
}

__device__ __forceinline__ void ceX(unsigned long long &v, int j, bool asc, int lane) {
    unsigned long long pv = __shfl_xor_sync(FULL, v, j);
    bool keepmin = (((lane & j) == 0) == asc);
    unsigned long long mn = v < pv ? v : pv;
    unsigned long long mx = v < pv ? pv : v;
    v = keepmin ? mn : mx;
}

// ---- kernel 1: bin points into 16x16 grid, once per sample ----
__global__ void __launch_bounds__(256) bin_kernel(
    const float* __restrict__ ix, const float* __restrict__ iy)
{
    __shared__ int cnts[NCELL];
    __shared__ int wsum[8];
    const int s = blockIdx.x, tid = threadIdx.x;
    const int lane = tid & 31, w = tid >> 5;

    cnts[tid] = 0;
    __syncthreads();
    for (int i = tid; i < NPTS; i += 256) {
        float px = ix[s * NPTS + i], py = iy[s * NPTS + i];
        int cx = min(GD - 1, (int)(px * GD));
        int cy = min(GD - 1, (int)(py * GD));
        atomicAdd(&cnts[cy * GD + cx], 1);
    }
    __syncthreads();
    int v = cnts[tid];
    int inc = v;
#pragma unroll
    for (int o = 1; o < 32; o <<= 1) {
        int t = __shfl_up_sync(FULL, inc, o);
        if (lane >= o) inc += t;
    }
    if (lane == 31) wsum[w] = inc;
    __syncthreads();
    int base = 0;
    for (int k = 0; k < w; k++) base += wsum[k];
    int excl = base + inc - v;
    __syncthreads();
    cnts[tid] = excl;
    g_cs[s][tid] = excl;
    if (tid == 255) g_cs[s][NCELL] = excl + v;
    __syncthreads();
    for (int i = tid; i < NPTS; i += 256) {
        float px = ix[s * NPTS + i], py = iy[s * NPTS + i];
        int cx = min(GD - 1, (int)(px * GD));
        int cy = min(GD - 1, (int)(py * GD));
        int pos = atomicAdd(&cnts[cy * GD + cx], 1);
        g_xy[s][pos] = make_float2(px, py);
        g_id[s][pos] = (unsigned short)i;
    }
}

// ---- kernel 2: per-warp query KNN + MLP-softmax blend ----
__global__ void __launch_bounds__(TPB, 4) knn_main(
    const float* __restrict__ u,
    const float* __restrict__ qx, const float* __restrict__ qy,
    const float* __restrict__ W1, const float* __restrict__ b1,
    const float* __restrict__ W2,
    float* __restrict__ out, int Q)
{
    __shared__ float2 sxy[NPTS];                     // 32 KB
    __shared__ unsigned short sid[NPTS];             // 8 KB
    __shared__ int cs[NCELL + 1];
    __shared__ unsigned long long buf[WARPS][CAP];   // 8 KB
    __shared__ float c1x[HID], c1y[HID], cb[HID], w2m[HID];
    __shared__ float sW2sum;

    const int s    = blockIdx.y;
    const int tid  = threadIdx.x;
    const int lane = tid & 31;
    const int w    = tid >> 5;

    for (int i = tid; i < NPTS; i += TPB) { sxy[i] = g_xy[s][i]; sid[i] = g_id[s][i]; }
    if (tid <= NCELL) cs[tid] = g_cs[s][tid];
    if (tid < HID) {
        c1x[tid] = TWO_LOG2E * W1[tid];          // 2*log2e*W1[0][i]
        c1y[tid] = TWO_LOG2E * W1[HID + tid];    // 2*log2e*W1[1][i]
        cb[tid]  = TWO_LOG2E * b1[tid];
        w2m[tid] = -2.0f * W2[tid];
    }
    if (tid == 0) {
        float acc = 0.0f;
        for (int i = 0; i < HID; i++) acc += W2[i];
        sW2sum = acc;
    }
    __syncthreads();

    const int qbase = blockIdx.x * (WARPS * QPW) + w * QPW;
    for (int qi = 0; qi < QPW; qi++) {
        const int q = qbase + qi;
        const float qxx = qx[s * Q + q];
        const float qyy = qy[s * Q + q];
        const float qn  = __fadd_rn(__fmul_rn(qxx, qxx), __fmul_rn(qyy, qyy));

        // threshold radius: clipped-disk area targeting ~44 points
        const float A = 44.0f / 4096.0f;
        float r = 0.05851f;                          // sqrt(A/pi)
        const float mnx = fminf(qxx, 1.0f - qxx);
        const float mny = fminf(qyy, 1.0f - qyy);
        if (mnx < r || mny < r) {
#pragma unroll
            for (int it = 0; it < 2; it++) {
                float ax = fminf(mnx / r, 1.0f);
                float ay = fminf(mny / r, 1.0f);
                float fx = 1.0f - (acosf(ax) - ax * sqrtf(fmaxf(0.f, 1.f - ax * ax))) / PI_F;
                float fy = 1.0f - (acosf(ay) - ay * sqrtf(fmaxf(0.f, 1.f - ay * ay))) / PI_F;
                r = sqrtf(A / (PI_F * fx * fy));
            }
        }
        float T = r * r;

        int cnt = 0;
        for (int attempt = 0; attempt < 8; attempt++) {
            cnt = 0;
            const float rr = sqrtf(T) * 1.0002f;     // d2-rounding slack
            const int cx0 = max(0,      (int)floorf((qxx - rr) * GD));
            const int cx1 = min(GD - 1, (int)floorf((qxx + rr) * GD));
            const int cy0 = max(0,      (int)floorf((qyy - rr) * GD));
            const int cy1 = min(GD - 1, (int)floorf((qyy + rr) * GD));
            for (int cy = cy0; cy <= cy1; cy++) {
                const int b0  = cs[cy * GD + cx0];
                const int b1e = cs[cy * GD + cx1 + 1];
                for (int base = b0; base < b1e; base += 32) {
                    const int j = base + lane;
                    const bool act = (j < b1e);
                    float2 p = act ? sxy[j] : make_float2(1e9f, 1e9f);
                    float dd = d2_ref(qxx, qyy, qn, p.x, p.y);
                    bool acc = act && (dd <= T);
                    unsigned m = __ballot_sync(FULL, acc);
                    if (acc) {
                        int off = cnt + __popc(m & ((1u << lane) - 1u));
                        if (off < CAP) {
                            unsigned id = sid[j];
                            buf[w][off] = ((unsigned long long)fkey(dd) << 24)
                                        | ((unsigned long long)id << 12)
                                        | (unsigned long long)j;
                        }
                    }
                    cnt += __popc(m);
                }
            }
            if (cnt >= KN && cnt <= CAP) break;
            T *= (cnt > CAP) ? (50.0f / (float)cnt)
                             : (45.0f / fmaxf((float)cnt, 8.0f));
        }

        // ---- exact smallest-32 selection (sorted) from <=64 keys ----
        const int n = min(cnt, CAP);
        unsigned long long v0 = (lane      < n) ? buf[w][lane]      : MAXK;
        unsigned long long v1 = (32 + lane < n) ? buf[w][32 + lane] : MAXK;
#pragma unroll
        for (int k = 2; k <= 16; k <<= 1) {
#pragma unroll
            for (int j = k >> 1; j > 0; j >>= 1) {
                bool asc = ((lane & k) == 0);
                ceX(v0, j, asc, lane);
                ceX(v1, j, asc, lane);
            }
        }
#pragma unroll
        for (int j = 16; j > 0; j >>= 1) { ceX(v0, j, true, lane); ceX(v1, j, false, lane); }
        v0 = (v0 < v1) ? v0 : v1;
#pragma unroll
        for (int j = 16; j > 0; j >>= 1) ceX(v0, j, true, lane);
        // lanes 0..29 hold exact lex top-30 (d2, id) ascending

        // ---- epilogue: logit = sumW2 - sum 2*W2/(exp2(c.rel)+1)  (MUFU) ----
        float logit = __int_as_float(0xff800000);
        float lab = 0.0f;
        if (lane < KN) {
            const int pos = (int)(v0 & 0xFFFULL);
            const int id  = (int)((v0 >> 12) & 0xFFFULL);
            const float2 p = sxy[pos];
            lab = u[s * NPTS + id];
            const float rx = p.x - qxx;
            const float ry = p.y - qyy;
            float acc = 0.0f;
#pragma unroll
            for (int i = 0; i < HID; i++) {
                float t = ex2(fmaf(rx, c1x[i], fmaf(ry, c1y[i], cb[i])));
                acc = fmaf(w2m[i], rcp(t + 1.0f), acc);
            }
            logit = acc + sW2sum;        // b2 cancels in softmax
        }
        float lmax = logit;
#pragma unroll
        for (int o = 16; o; o >>= 1) lmax = fmaxf(lmax, __shfl_xor_sync(FULL, lmax, o));
        const float wgt = (lane < KN) ? __expf(logit - lmax) : 0.0f;
        float ws = wgt, os = wgt * lab;
#pragma unroll
        for (int o = 16; o; o >>= 1) {
            ws += __shfl_xor_sync(FULL, ws, o);
            os += __shfl_xor_sync(FULL, os, o);
        }
        if (lane == 0) out[s * Q + q] = __fdividef(os, ws);
    }
}

extern "C" void kernel_launch(void* const* d_in, const int* in_sizes, int n_in,
                              void* d_out, int out_size) {
    const float* u  = (const float*)d_in[0];
    const float* ix = (const float*)d_in[1];
    const float* iy = (const float*)d_in[2];
    const float* x  = (const float*)d_in[3];
    const float* y  = (const float*)d_in[4];
    const float* W1 = (const float*)d_in[5];
    const float* b1 = (const float*)d_in[6];
    const float* W2 = (const float*)d_in[7];
    // d_in[8] = b2 : constant shift, cancels in softmax
    float* out = (float*)d_out;

    const int nu = in_sizes[0] / NPTS;   // 4
    const int Q  = in_sizes[3] / nu;     // 16384

    bin_kernel<<<nu, 256>>>(ix, iy);

    dim3 grid(Q / (WARPS * QPW), nu);    // (256, 4)
    knn_main<<<grid, TPB>>>(u, x, y, W1, b1, W2, out, Q);
}

// round 13
// speedup vs baseline: 1.0349x; 1.0349x over previous
#include <cuda_runtime.h>
#include <math.h>

#define NPTS 4096
#define KN   30
#define HID  32
#define GD   16
#define NCELL 256
#define CAP  64
#define TPB  512
#define WARPS 16
#define QPW  4
#define MAXNU 8
#define FULL 0xffffffffu
#define MAXK 0xffffffffffffffffULL
#define PI_F 3.14159265358979f
#define TWO_LOG2E 2.885390081777927f   // 2*log2(e)

__device__ float2         g_xy[MAXNU][NPTS];
__device__ unsigned short g_id[MAXNU][NPTS];
__device__ int            g_cs[MAXNU][NCELL + 1];

// FROZEN reference rounding chain (validated bit-exact R7-R12):
//   pn = rn( rn(px*px) + rn(py*py) )
//   t  = fma(qy,py, rn(qx*px))
//   d2 = rn( rn(qn - 2t) + pn )
__device__ __forceinline__ float d2_ref(float qxx, float qyy, float qn,
                                        float px, float py) {
    float pn = __fadd_rn(__fmul_rn(px, px), __fmul_rn(py, py));
    float t  = __fmaf_rn(qyy, py, __fmul_rn(qxx, px));
    return __fadd_rn(__fsub_rn(qn, __fmul_rn(2.0f, t)), pn);
}

__device__ __forceinline__ unsigned fkey(float f) {
    unsigned u = __float_as_uint(f);
    return u ^ (unsigned)(((int)u >> 31) | 0x80000000);
}

__device__ __forceinline__ float ex2(float x) {
    float r; asm("ex2.approx.f32 %0, %1;" : "=f"(r) : "f"(x)); return r;
}
__device__ __forceinline__ float rcp(float x) {
    float r; asm("rcp.approx.f32 %0, %1;" : "=f"(r) : "f"(x)); return r;
}

__device__ __forceinline__ void ceX(unsigned long long &v, int j, bool asc, int lane) {
    unsigned long long pv = __shfl_xor_sync(FULL, v, j);
    bool keepmin = (((lane & j) == 0) == asc);
    unsigned long long mn = v < pv ? v : pv;
    unsigned long long mx = v < pv ? pv : v;
    v = keepmin ? mn : mx;
}

// ---- kernel 1: bin points into 16x16 grid, once per sample ----
__global__ void __launch_bounds__(256) bin_kernel(
    const float* __restrict__ ix, const float* __restrict__ iy)
{
    __shared__ int cnts[NCELL];
    __shared__ int wsum[8];
    const int s = blockIdx.x, tid = threadIdx.x;
    const int lane = tid & 31, w = tid >> 5;

    cnts[tid] = 0;
    __syncthreads();
    for (int i = tid; i < NPTS; i += 256) {
        float px = ix[s * NPTS + i], py = iy[s * NPTS + i];
        int cx = min(GD - 1, (int)(px * GD));
        int cy = min(GD - 1, (int)(py * GD));
        atomicAdd(&cnts[cy * GD + cx], 1);
    }
    __syncthreads();
    int v = cnts[tid];
    int inc = v;
#pragma unroll
    for (int o = 1; o < 32; o <<= 1) {
        int t = __shfl_up_sync(FULL, inc, o);
        if (lane >= o) inc += t;
    }
    if (lane == 31) wsum[w] = inc;
    __syncthreads();
    int base = 0;
    for (int k = 0; k < w; k++) base += wsum[k];
    int excl = base + inc - v;
    __syncthreads();
    cnts[tid] = excl;
    g_cs[s][tid] = excl;
    if (tid == 255) g_cs[s][NCELL] = excl + v;
    __syncthreads();
    for (int i = tid; i < NPTS; i += 256) {
        float px = ix[s * NPTS + i], py = iy[s * NPTS + i];
        int cx = min(GD - 1, (int)(px * GD));
        int cy = min(GD - 1, (int)(py * GD));
        int pos = atomicAdd(&cnts[cy * GD + cx], 1);
        g_xy[s][pos] = make_float2(px, py);
        g_id[s][pos] = (unsigned short)i;
    }
}

// ---- kernel 2: per-warp query KNN + MLP-softmax blend ----
__global__ void __launch_bounds__(TPB, 3) knn_main(
    const float* __restrict__ u,
    const float* __restrict__ qx, const float* __restrict__ qy,
    const float* __restrict__ W1, const float* __restrict__ b1,
    const float* __restrict__ W2,
    float* __restrict__ out, int Q)
{
    __shared__ float2 sxy[NPTS];                     // 32 KB
    __shared__ unsigned short sid[NPTS];             // 8 KB
    __shared__ int cs[NCELL + 1];
    __shared__ unsigned long long buf[WARPS][CAP];   // 8 KB
    __shared__ float c1x[HID], c1y[HID], cb[HID], w2m[HID];
    __shared__ float sW2sum;

    const int s    = blockIdx.y;
    const int tid  = threadIdx.x;
    const int lane = tid & 31;
    const int w    = tid >> 5;

    for (int i = tid; i < NPTS; i += TPB) { sxy[i] = g_xy[s][i]; sid[i] = g_id[s][i]; }
    if (tid <= NCELL) cs[tid] = g_cs[s][tid];
    if (tid < HID) {
        c1x[tid] = TWO_LOG2E * W1[tid];          // 2*log2e*W1[0][i]
        c1y[tid] = TWO_LOG2E * W1[HID + tid];    // 2*log2e*W1[1][i]
        cb[tid]  = TWO_LOG2E * b1[tid];
        w2m[tid] = -2.0f * W2[tid];
    }
    if (tid == 0) {
        float acc = 0.0f;
        for (int i = 0; i < HID; i++) acc += W2[i];
        sW2sum = acc;
    }
    __syncthreads();

    const int qbase = blockIdx.x * (WARPS * QPW) + w * QPW;
    for (int qi = 0; qi < QPW; qi++) {
        const int q = qbase + qi;
        const float qxx = qx[s * Q + q];
        const float qyy = qy[s * Q + q];
        const float qn  = __fadd_rn(__fmul_rn(qxx, qxx), __fmul_rn(qyy, qyy));

        // threshold radius: clipped-disk area targeting ~44 points
        const float A = 44.0f / 4096.0f;
        float r = 0.05851f;                          // sqrt(A/pi)
        const float mnx = fminf(qxx, 1.0f - qxx);
        const float mny = fminf(qyy, 1.0f - qyy);
        if (mnx < r || mny < r) {
#pragma unroll
            for (int it = 0; it < 2; it++) {
                float ax = fminf(mnx / r, 1.0f);
                float ay = fminf(mny / r, 1.0f);
                float fx = 1.0f - (acosf(ax) - ax * sqrtf(fmaxf(0.f, 1.f - ax * ax))) / PI_F;
                float fy = 1.0f - (acosf(ay) - ay * sqrtf(fmaxf(0.f, 1.f - ay * ay))) / PI_F;
                r = sqrtf(A / (PI_F * fx * fy));
            }
        }
        float T = r * r;

        int cnt = 0;
        for (int attempt = 0; attempt < 8; attempt++) {
            cnt = 0;
            const float rr = sqrtf(T) * 1.0002f;     // d2-rounding slack
            const int cx0 = max(0,      (int)floorf((qxx - rr) * GD));
            const int cx1 = min(GD - 1, (int)floorf((qxx + rr) * GD));
            const int cy0 = max(0,      (int)floorf((qyy - rr) * GD));
            const int cy1 = min(GD - 1, (int)floorf((qyy + rr) * GD));
            for (int cy = cy0; cy <= cy1; cy++) {
                const int b0  = cs[cy * GD + cx0];
                const int b1e = cs[cy * GD + cx1 + 1];
                for (int base = b0; base < b1e; base += 32) {
                    const int j = base + lane;
                    const bool act = (j < b1e);
                    float2 p = act ? sxy[j] : make_float2(1e9f, 1e9f);
                    float dd = d2_ref(qxx, qyy, qn, p.x, p.y);
                    bool acc = act && (dd <= T);
                    unsigned m = __ballot_sync(FULL, acc);
                    if (acc) {
                        int off = cnt + __popc(m & ((1u << lane) - 1u));
                        if (off < CAP) {
                            unsigned id = sid[j];
                            buf[w][off] = ((unsigned long long)fkey(dd) << 24)
                                        | ((unsigned long long)id << 12)
                                        | (unsigned long long)j;
                        }
                    }
                    cnt += __popc(m);
                }
            }
            if (cnt >= KN && cnt <= CAP) break;
            T *= (cnt > CAP) ? (50.0f / (float)cnt)
                             : (45.0f / fmaxf((float)cnt, 8.0f));
        }

        // ---- exact smallest-32 selection (sorted) from <=64 keys ----
        const int n = min(cnt, CAP);
        unsigned long long v0 = (lane      < n) ? buf[w][lane]      : MAXK;
        unsigned long long v1 = (32 + lane < n) ? buf[w][32 + lane] : MAXK;
#pragma unroll
        for (int k = 2; k <= 16; k <<= 1) {
#pragma unroll
            for (int j = k >> 1; j > 0; j >>= 1) {
                bool asc = ((lane & k) == 0);
                ceX(v0, j, asc, lane);
                ceX(v1, j, asc, lane);
            }
        }
#pragma unroll
        for (int j = 16; j > 0; j >>= 1) { ceX(v0, j, true, lane); ceX(v1, j, false, lane); }
        v0 = (v0 < v1) ? v0 : v1;
#pragma unroll
        for (int j = 16; j > 0; j >>= 1) ceX(v0, j, true, lane);
        // lanes 0..29 hold exact lex top-30 (d2, id) ascending

        // ---- epilogue: logit = sumW2 - sum 2*W2/(exp2(c.rel)+1)  (MUFU) ----
        float logit = __int_as_float(0xff800000);
        float lab = 0.0f;
        if (lane < KN) {
            const int pos = (int)(v0 & 0xFFFULL);
            const int id  = (int)((v0 >> 12) & 0xFFFULL);
            const float2 p = sxy[pos];
            lab = u[s * NPTS + id];
            const float rx = p.x - qxx;
            const float ry = p.y - qyy;
            float acc = 0.0f;
#pragma unroll
            for (int i = 0; i < HID; i++) {
                float t = ex2(fmaf(rx, c1x[i], fmaf(ry, c1y[i], cb[i])));
                acc = fmaf(w2m[i], rcp(t + 1.0f), acc);
            }
            logit = acc + sW2sum;        // b2 cancels in softmax
        }
        float lmax = logit;
#pragma unroll
        for (int o = 16; o; o >>= 1) lmax = fmaxf(lmax, __shfl_xor_sync(FULL, lmax, o));
        const float wgt = (lane < KN) ? __expf(logit - lmax) : 0.0f;
        float ws = wgt, os = wgt * lab;
#pragma unroll
        for (int o = 16; o; o >>= 1) {
            ws += __shfl_xor_sync(FULL, ws, o);
            os += __shfl_xor_sync(FULL, os, o);
        }
        if (lane == 0) out[s * Q + q] = __fdividef(os, ws);
    }
}

extern "C" void kernel_launch(void* const* d_in, const int* in_sizes, int n_in,
                              void* d_out, int out_size) {
    const float* u  = (const float*)d_in[0];
    const float* ix = (const float*)d_in[1];
    const float* iy = (const float*)d_in[2];
    const float* x  = (const float*)d_in[3];
    const float* y  = (const float*)d_in[4];
    const float* W1 = (const float*)d_in[5];
    const float* b1 = (const float*)d_in[6];
    const float* W2 = (const float*)d_in[7];
    // d_in[8] = b2 : constant shift, cancels in softmax
    float* out = (float*)d_out;

    const int nu = in_sizes[0] / NPTS;   // 4
    const int Q  = in_sizes[3] / nu;     // 16384

    bin_kernel<<<nu, 256>>>(ix, iy);

    dim3 grid(Q / (WARPS * QPW), nu);    // (256, 4)
    knn_main<<<grid, TPB>>>(u, x, y, W1, b1, W2, out, Q);
}